// round 16
// baseline (speedup 1.0000x reference)
#include <cuda_runtime.h>
#include <cuda_fp16.h>
#include <cstdint>

// Problem shape (fixed by the dataset)
#define MM 8192
#define NN 4096
#define KK 4096

// GEMM tiling (fp16 operands)
#define BM 128
#define BN 128
#define BK 64               // fp16 elems = 128 data bytes per row
#define STAGES 3
#define NKT (KK / BK)       // 64
#define PAD_ROW 144         // 128 data + 16 pad: conflict-free, no XOR swizzle
#define A_TILE_BYTES (BM * PAD_ROW)          // 18432
#define B_TILE_BYTES (BN * PAD_ROW)          // 18432
#define STAGE_BYTES (A_TILE_BYTES + B_TILE_BYTES)   // 36864
#define SMEM_TOTAL (STAGES * STAGE_BYTES)           // 110592 -> 2 CTAs/SM

#define ROW_BYTES (KK * 2)               // 8192 bytes per logical gmem row
#define I_GSTRIDE (16 * ROW_BYTES)       // +16 rows in gmem (128 threads)
#define I_SSTRIDE (16 * PAD_ROW)         // +16 rows in smem tile

// Scratch: quantized activations + fp16 weights (static device arrays allowed)
__device__ __align__(16) __half g_xq[(size_t)MM * KK];
__device__ __align__(16) __half g_wb[(size_t)NN * KK];

__device__ __forceinline__ uint32_t s2u(const void* p) {
    return (uint32_t)__cvta_generic_to_shared(p);
}

__device__ __forceinline__ void ldsm_x4(uint32_t& r0, uint32_t& r1,
                                        uint32_t& r2, uint32_t& r3, uint32_t a) {
    asm volatile(
        "ldmatrix.sync.aligned.m8n8.x4.shared.b16 {%0,%1,%2,%3}, [%4];"
        : "=r"(r0), "=r"(r1), "=r"(r2), "=r"(r3) : "r"(a));
}

__device__ __forceinline__ void hmma(float* c, uint32_t a0, uint32_t a1, uint32_t a2,
                                     uint32_t a3, uint32_t b0, uint32_t b1) {
    asm volatile(
        "mma.sync.aligned.m16n8k16.row.col.f32.f16.f16.f32 "
        "{%0,%1,%2,%3}, {%4,%5,%6,%7}, {%8,%9}, {%0,%1,%2,%3};"
        : "+f"(c[0]), "+f"(c[1]), "+f"(c[2]), "+f"(c[3])
        : "r"(a0), "r"(a1), "r"(a2), "r"(a3), "r"(b0), "r"(b1));
}

__device__ __forceinline__ void cpa16(uint32_t dst, const void* src) {
    asm volatile("cp.async.cg.shared.global [%0], [%1], 16;"
                 :: "r"(dst), "l"(src) : "memory");
}

// ---------------------------------------------------------------------------
// Kernel 1 (fused prep, 2-wide ILP):
//   blocks [0, XBLK)          : x -> fp16(clip(round(x/s_in)))
//   blocks [XBLK, XBLK+WBLK)  : W int32 -> fp16 (exact)
// ---------------------------------------------------------------------------
#define XQ4 (MM * KK / 4)
#define WQ4 (NN * KK / 4)
#define XBLK (XQ4 / 2 / 256)
#define WBLK (WQ4 / 2 / 256)

__global__ void prep_kernel(const float* __restrict__ x,
                            const int* __restrict__ w,
                            const float* __restrict__ iscale) {
    int b = blockIdx.x;
    if (b < XBLK) {
        int i = b * 256 + threadIdx.x;
        float inv = 1.0f / iscale[0];
        float4 v0 = reinterpret_cast<const float4*>(x)[i];
        float4 v1 = reinterpret_cast<const float4*>(x)[i + XQ4 / 2];
        float a0 = fminf(fmaxf(rintf(v0.x * inv), -128.0f), 127.0f);
        float a1 = fminf(fmaxf(rintf(v0.y * inv), -128.0f), 127.0f);
        float a2 = fminf(fmaxf(rintf(v0.z * inv), -128.0f), 127.0f);
        float a3 = fminf(fmaxf(rintf(v0.w * inv), -128.0f), 127.0f);
        float b0 = fminf(fmaxf(rintf(v1.x * inv), -128.0f), 127.0f);
        float b1 = fminf(fmaxf(rintf(v1.y * inv), -128.0f), 127.0f);
        float b2 = fminf(fmaxf(rintf(v1.z * inv), -128.0f), 127.0f);
        float b3 = fminf(fmaxf(rintf(v1.w * inv), -128.0f), 127.0f);
        __half2* o0 = reinterpret_cast<__half2*>(g_xq) + (size_t)i * 2;
        __half2* o1 = reinterpret_cast<__half2*>(g_xq) + ((size_t)i + XQ4 / 2) * 2;
        o0[0] = __floats2half2_rn(a0, a1);
        o0[1] = __floats2half2_rn(a2, a3);
        o1[0] = __floats2half2_rn(b0, b1);
        o1[1] = __floats2half2_rn(b2, b3);
    } else {
        int i = (b - XBLK) * 256 + threadIdx.x;
        int4 v0 = reinterpret_cast<const int4*>(w)[i];
        int4 v1 = reinterpret_cast<const int4*>(w)[i + WQ4 / 2];
        __half2* o0 = reinterpret_cast<__half2*>(g_wb) + (size_t)i * 2;
        __half2* o1 = reinterpret_cast<__half2*>(g_wb) + ((size_t)i + WQ4 / 2) * 2;
        o0[0] = __floats2half2_rn((float)v0.x, (float)v0.y);
        o0[1] = __floats2half2_rn((float)v0.z, (float)v0.w);
        o1[0] = __floats2half2_rn((float)v1.x, (float)v1.y);
        o1[1] = __floats2half2_rn((float)v1.z, (float)v1.w);
    }
}

// ---------------------------------------------------------------------------
// Kernel 2: fp16 HMMA GEMM, 128 threads = 4 warps in 2x2 grid of 64x64 tiles.
// Padded-row layout: LDSM k-step offset is a compile-time immediate.
// ---------------------------------------------------------------------------
struct Frag { uint32_t a[4][4]; uint32_t b[4][4]; };

// aad/bad: 8 absolute smem addresses (4 A row-tiles, 4 B row-tiles), J = k-step
template<int J>
__device__ __forceinline__ void frags_ld(Frag& f, const uint32_t* aad,
                                         const uint32_t* bad) {
#pragma unroll
    for (int mt = 0; mt < 4; ++mt)
        ldsm_x4(f.a[mt][0], f.a[mt][1], f.a[mt][2], f.a[mt][3],
                aad[mt] + J * 32);
#pragma unroll
    for (int p = 0; p < 4; ++p)
        ldsm_x4(f.b[p][0], f.b[p][1], f.b[p][2], f.b[p][3],
                bad[p] + J * 32);
}

__device__ __forceinline__ void frags_mma(float acc[4][8][4], const Frag& f) {
#pragma unroll
    for (int mt = 0; mt < 4; ++mt)
#pragma unroll
        for (int p = 0; p < 4; ++p) {
            hmma(acc[mt][2 * p],     f.a[mt][0], f.a[mt][1], f.a[mt][2],
                 f.a[mt][3], f.b[p][0], f.b[p][2]);
            hmma(acc[mt][2 * p + 1], f.a[mt][0], f.a[mt][1], f.a[mt][2],
                 f.a[mt][3], f.b[p][1], f.b[p][3]);
        }
}

__global__ void __launch_bounds__(128, 2)
gemm_kernel(float* __restrict__ out,
            const float* __restrict__ scale, const float* __restrict__ iscale) {
    extern __shared__ char smem[];
    uint32_t sb = s2u(smem);
    int tid = threadIdx.x;
    int wid = tid >> 5, lid = tid & 31;
    int wm = wid >> 1, wn = wid & 1;          // 2x2 warps, 64x64 each

    int tm = blockIdx.x & (MM / BM - 1);      // m fast -> ktile slices stay in L2
    int tn = blockIdx.x >> 6;                 // MM/BM = 64

    // per-thread cp.async bases (row = tid>>3 in 16-row group, ch = tid&7)
    int prow = tid >> 3, pch = tid & 7;
    const char* aptr = reinterpret_cast<const char*>(g_xq)
                     + (size_t)(tm * BM + prow) * ROW_BYTES + pch * 16;
    const char* bptr = reinterpret_cast<const char*>(g_wb)
                     + (size_t)(tn * BN + prow) * ROW_BYTES + pch * 16;
    uint32_t dbase_a = (uint32_t)prow * PAD_ROW + (uint32_t)pch * 16;
    uint32_t dbase_b = dbase_a + A_TILE_BYTES;

    float acc[4][8][4];                        // 128 regs
#pragma unroll
    for (int i = 0; i < 4; ++i)
#pragma unroll
        for (int j = 0; j < 8; ++j)
#pragma unroll
            for (int k = 0; k < 4; ++k) acc[i][j][k] = 0.0f;

    // stage-relative LDSM offsets (8 regs); j-step is an LDSM immediate (+32j)
    int lrow = lid & 15;
    uint32_t lhi16 = (uint32_t)(lid >> 4) << 4;
    uint32_t relA[4], relB[4];
#pragma unroll
    for (int mt = 0; mt < 4; ++mt)
        relA[mt] = (uint32_t)(wm * 64 + mt * 16 + lrow) * PAD_ROW + lhi16;
#pragma unroll
    for (int p = 0; p < 4; ++p)
        relB[p] = (uint32_t)(wn * 64 + p * 16 + lrow) * PAD_ROW + lhi16
                + A_TILE_BYTES;

    // prologue: fill STAGES-1 stages (8 A-chunks + 8 B-chunks per thread)
#pragma unroll
    for (int s = 0; s < STAGES - 1; ++s) {
#pragma unroll
        for (int i = 0; i < 8; ++i)
            cpa16(sb + s * STAGE_BYTES + dbase_a + i * I_SSTRIDE,
                  aptr + i * I_GSTRIDE);
#pragma unroll
        for (int i = 0; i < 8; ++i)
            cpa16(sb + s * STAGE_BYTES + dbase_b + i * I_SSTRIDE,
                  bptr + i * I_GSTRIDE);
        asm volatile("cp.async.commit_group;" ::: "memory");
        aptr += BK * 2;
        bptr += BK * 2;
    }

    uint32_t cur = sb;
    uint32_t lda = sb + (STAGES - 1) * STAGE_BYTES + dbase_a;
    uint32_t ldb = sb + (STAGES - 1) * STAGE_BYTES + dbase_b;
    const uint32_t wrap = sb + STAGES * STAGE_BYTES;

    // main loop: unconditional loads
    for (int kt = 0; kt < NKT - (STAGES - 1); ++kt) {
        asm volatile("cp.async.wait_group %0;" :: "n"(STAGES - 2) : "memory");
        __syncthreads();

        // 8 absolute LDSM base addresses for this stage (8 IADDs)
        uint32_t aad[4], bad[4];
#pragma unroll
        for (int mt = 0; mt < 4; ++mt) aad[mt] = cur + relA[mt];
#pragma unroll
        for (int p = 0; p < 4; ++p)    bad[p] = cur + relB[p];

        Frag f0, f1;
        frags_ld<0>(f0, aad, bad);             // j=0 first: restart tensor pipe

#pragma unroll
        for (int i = 0; i < 8; ++i)
            cpa16(lda + i * I_SSTRIDE, aptr + i * I_GSTRIDE);
#pragma unroll
        for (int i = 0; i < 8; ++i)
            cpa16(ldb + i * I_SSTRIDE, bptr + i * I_GSTRIDE);
        aptr += BK * 2;
        bptr += BK * 2;
        asm volatile("cp.async.commit_group;" ::: "memory");

        frags_ld<1>(f1, aad, bad);
        frags_mma(acc, f0);
        frags_ld<2>(f0, aad, bad);
        frags_mma(acc, f1);
        frags_ld<3>(f1, aad, bad);
        frags_mma(acc, f0);
        frags_mma(acc, f1);

        cur += STAGE_BYTES; if (cur == wrap) cur = sb;
        lda += STAGE_BYTES; if (lda >= wrap) lda -= STAGES * STAGE_BYTES;
        ldb += STAGE_BYTES; if (ldb >= wrap) ldb -= STAGES * STAGE_BYTES;
    }

    // tail: last STAGES-1 ktiles, no loads
#pragma unroll
    for (int t = 0; t < STAGES - 1; ++t) {
        asm volatile("cp.async.wait_group %0;" :: "n"(0) : "memory");
        __syncthreads();
        uint32_t aad[4], bad[4];
#pragma unroll
        for (int mt = 0; mt < 4; ++mt) aad[mt] = cur + relA[mt];
#pragma unroll
        for (int p = 0; p < 4; ++p)    bad[p] = cur + relB[p];
        Frag f0, f1;
        frags_ld<0>(f0, aad, bad);
        frags_ld<1>(f1, aad, bad);
        frags_mma(acc, f0);
        frags_ld<2>(f0, aad, bad);
        frags_mma(acc, f1);
        frags_ld<3>(f1, aad, bad);
        frags_mma(acc, f0);
        frags_mma(acc, f1);
        cur += STAGE_BYTES; if (cur == wrap) cur = sb;
    }

    // epilogue: scale and store fp32
    float cs = scale[0] * iscale[0];
    int r0 = lid >> 2, c0 = (lid & 3) * 2;
#pragma unroll
    for (int mt = 0; mt < 4; ++mt) {
        size_t row0 = (size_t)tm * BM + wm * 64 + mt * 16 + r0;
#pragma unroll
        for (int nt = 0; nt < 8; ++nt) {
            size_t col = (size_t)tn * BN + wn * 64 + nt * 8 + c0;
            float2 v0, v1;
            v0.x = acc[mt][nt][0] * cs;
            v0.y = acc[mt][nt][1] * cs;
            v1.x = acc[mt][nt][2] * cs;
            v1.y = acc[mt][nt][3] * cs;
            *reinterpret_cast<float2*>(out + row0 * NN + col) = v0;
            *reinterpret_cast<float2*>(out + (row0 + 8) * NN + col) = v1;
        }
    }
}

// ---------------------------------------------------------------------------
extern "C" void kernel_launch(void* const* d_in, const int* in_sizes, int n_in,
                              void* d_out, int out_size) {
    const float* x      = (const float*)d_in[0];
    const int*   w      = (const int*)d_in[1];
    const float* scale  = (const float*)d_in[2];
    const float* iscale = (const float*)d_in[3];
    float* out = (float*)d_out;

    cudaFuncSetAttribute(gemm_kernel, cudaFuncAttributeMaxDynamicSharedMemorySize,
                         SMEM_TOTAL);

    prep_kernel<<<XBLK + WBLK, 256>>>(x, w, iscale);
    gemm_kernel<<<(MM / BM) * (NN / BN), 128, SMEM_TOTAL>>>(out, scale, iscale);
}

// round 17
// speedup vs baseline: 1.2119x; 1.2119x over previous
#include <cuda_runtime.h>
#include <cuda_fp16.h>
#include <cstdint>

// Problem shape (fixed by the dataset)
#define MM 8192
#define NN 4096
#define KK 4096

// GEMM tiling (fp16 operands)
#define BM 128
#define BN 128
#define BK 64               // fp16 elems = 128 bytes = one swizzled row
#define STAGES 3
#define NKT (KK / BK)       // 64
#define A_TILE_BYTES (BM * 128)          // 16384
#define B_TILE_BYTES (BN * 128)          // 16384
#define STAGE_BYTES (A_TILE_BYTES + B_TILE_BYTES)   // 32768
#define SMEM_TOTAL (STAGES * STAGE_BYTES)           // 98304 -> 2 CTAs/SM

#define ROW_BYTES (KK * 2)               // 8192 bytes per logical gmem row
#define I_GSTRIDE (16 * ROW_BYTES)       // +16 rows in gmem (128 threads)
#define I_SSTRIDE (16 * 128)             // +16 rows in smem tile

// Scratch: quantized activations + fp16 weights (static device arrays allowed)
__device__ __align__(16) __half g_xq[(size_t)MM * KK];
__device__ __align__(16) __half g_wb[(size_t)NN * KK];

__device__ __forceinline__ uint32_t s2u(const void* p) {
    return (uint32_t)__cvta_generic_to_shared(p);
}

__device__ __forceinline__ void ldsm_x4(uint32_t& r0, uint32_t& r1,
                                        uint32_t& r2, uint32_t& r3, uint32_t a) {
    asm volatile(
        "ldmatrix.sync.aligned.m8n8.x4.shared.b16 {%0,%1,%2,%3}, [%4];"
        : "=r"(r0), "=r"(r1), "=r"(r2), "=r"(r3) : "r"(a));
}

__device__ __forceinline__ void hmma(float* c, uint32_t a0, uint32_t a1, uint32_t a2,
                                     uint32_t a3, uint32_t b0, uint32_t b1) {
    asm volatile(
        "mma.sync.aligned.m16n8k16.row.col.f32.f16.f16.f32 "
        "{%0,%1,%2,%3}, {%4,%5,%6,%7}, {%8,%9}, {%0,%1,%2,%3};"
        : "+f"(c[0]), "+f"(c[1]), "+f"(c[2]), "+f"(c[3])
        : "r"(a0), "r"(a1), "r"(a2), "r"(a3), "r"(b0), "r"(b1));
}

__device__ __forceinline__ void cpa16(uint32_t dst, const void* src) {
    asm volatile("cp.async.cg.shared.global [%0], [%1], 16;"
                 :: "r"(dst), "l"(src) : "memory");
}

// ---------------------------------------------------------------------------
// Kernel 1 (fused prep, 2-wide ILP):
//   blocks [0, XBLK)          : x -> fp16(clip(round(x/s_in)))
//   blocks [XBLK, XBLK+WBLK)  : W int32 -> fp16 (exact)
// ---------------------------------------------------------------------------
#define XQ4 (MM * KK / 4)
#define WQ4 (NN * KK / 4)
#define XBLK (XQ4 / 2 / 256)
#define WBLK (WQ4 / 2 / 256)

__global__ void prep_kernel(const float* __restrict__ x,
                            const int* __restrict__ w,
                            const float* __restrict__ iscale) {
    int b = blockIdx.x;
    if (b < XBLK) {
        int i = b * 256 + threadIdx.x;
        float inv = 1.0f / iscale[0];
        float4 v0 = reinterpret_cast<const float4*>(x)[i];
        float4 v1 = reinterpret_cast<const float4*>(x)[i + XQ4 / 2];
        float a0 = fminf(fmaxf(rintf(v0.x * inv), -128.0f), 127.0f);
        float a1 = fminf(fmaxf(rintf(v0.y * inv), -128.0f), 127.0f);
        float a2 = fminf(fmaxf(rintf(v0.z * inv), -128.0f), 127.0f);
        float a3 = fminf(fmaxf(rintf(v0.w * inv), -128.0f), 127.0f);
        float b0 = fminf(fmaxf(rintf(v1.x * inv), -128.0f), 127.0f);
        float b1 = fminf(fmaxf(rintf(v1.y * inv), -128.0f), 127.0f);
        float b2 = fminf(fmaxf(rintf(v1.z * inv), -128.0f), 127.0f);
        float b3 = fminf(fmaxf(rintf(v1.w * inv), -128.0f), 127.0f);
        __half2* o0 = reinterpret_cast<__half2*>(g_xq) + (size_t)i * 2;
        __half2* o1 = reinterpret_cast<__half2*>(g_xq) + ((size_t)i + XQ4 / 2) * 2;
        o0[0] = __floats2half2_rn(a0, a1);
        o0[1] = __floats2half2_rn(a2, a3);
        o1[0] = __floats2half2_rn(b0, b1);
        o1[1] = __floats2half2_rn(b2, b3);
    } else {
        int i = (b - XBLK) * 256 + threadIdx.x;
        int4 v0 = reinterpret_cast<const int4*>(w)[i];
        int4 v1 = reinterpret_cast<const int4*>(w)[i + WQ4 / 2];
        __half2* o0 = reinterpret_cast<__half2*>(g_wb) + (size_t)i * 2;
        __half2* o1 = reinterpret_cast<__half2*>(g_wb) + ((size_t)i + WQ4 / 2) * 2;
        o0[0] = __floats2half2_rn((float)v0.x, (float)v0.y);
        o0[1] = __floats2half2_rn((float)v0.z, (float)v0.w);
        o1[0] = __floats2half2_rn((float)v1.x, (float)v1.y);
        o1[1] = __floats2half2_rn((float)v1.z, (float)v1.w);
    }
}

// ---------------------------------------------------------------------------
// Kernel 2: fp16 HMMA GEMM, 128 threads = 4 warps in 2x2 grid of 64x64 tiles.
// XOR-swizzled smem (r13 layout); cp.async interleaved through the k-steps.
// ---------------------------------------------------------------------------
struct Frag { uint32_t a[4][4]; uint32_t b[4][4]; };

__device__ __forceinline__ void frags_ld(Frag& f, uint32_t sa, uint32_t sbw,
                                         const uint32_t* offa, const uint32_t* offb) {
#pragma unroll
    for (int mt = 0; mt < 4; ++mt)
        ldsm_x4(f.a[mt][0], f.a[mt][1], f.a[mt][2], f.a[mt][3], sa + offa[mt]);
#pragma unroll
    for (int p = 0; p < 4; ++p)
        ldsm_x4(f.b[p][0], f.b[p][1], f.b[p][2], f.b[p][3], sbw + offb[p]);
}

__device__ __forceinline__ void frags_mma(float acc[4][8][4], const Frag& f) {
#pragma unroll
    for (int mt = 0; mt < 4; ++mt)
#pragma unroll
        for (int p = 0; p < 4; ++p) {
            hmma(acc[mt][2 * p],     f.a[mt][0], f.a[mt][1], f.a[mt][2],
                 f.a[mt][3], f.b[p][0], f.b[p][2]);
            hmma(acc[mt][2 * p + 1], f.a[mt][0], f.a[mt][1], f.a[mt][2],
                 f.a[mt][3], f.b[p][1], f.b[p][3]);
        }
}

__global__ void __launch_bounds__(128, 2)
gemm_kernel(float* __restrict__ out,
            const float* __restrict__ scale, const float* __restrict__ iscale) {
    extern __shared__ char smem[];
    uint32_t sb = s2u(smem);
    int tid = threadIdx.x;
    int wid = tid >> 5, lid = tid & 31;
    int wm = wid >> 1, wn = wid & 1;          // 2x2 warps, 64x64 each

    int tm = blockIdx.x & (MM / BM - 1);      // m fast -> ktile slices stay in L2
    int tn = blockIdx.x >> 6;                 // MM/BM = 64

    // per-thread cp.async bases (row = tid>>3 in 16-row group, ch = tid&7)
    int prow = tid >> 3, pch = tid & 7;
    const char* aptr = reinterpret_cast<const char*>(g_xq)
                     + (size_t)(tm * BM + prow) * ROW_BYTES + pch * 16;
    const char* bptr = reinterpret_cast<const char*>(g_wb)
                     + (size_t)(tn * BN + prow) * ROW_BYTES + pch * 16;
    uint32_t dbase_a = (uint32_t)prow * 128
                     + ((uint32_t)(pch ^ (prow & 7)) << 4);
    uint32_t dbase_b = dbase_a + A_TILE_BYTES;

    float acc[4][8][4];                        // 128 regs
#pragma unroll
    for (int i = 0; i < 4; ++i)
#pragma unroll
        for (int j = 0; j < 8; ++j)
#pragma unroll
            for (int k = 0; k < 4; ++k) acc[i][j][k] = 0.0f;

    // fully precomputed stage-relative LDSM offsets: [j][row-tile], 32 regs
    int lrow = lid & 15;
    uint32_t lhish = (uint32_t)(lid >> 4) << 4;
    uint32_t offa[4][4], offb[4][4];
#pragma unroll
    for (int j = 0; j < 4; ++j) {
        uint32_t chsh = ((uint32_t)(2 * j) << 4) ^ lhish;
#pragma unroll
        for (int mt = 0; mt < 4; ++mt) {
            int row = wm * 64 + mt * 16 + lrow;
            offa[j][mt] = (uint32_t)row * 128 + (chsh ^ ((uint32_t)(row & 7) << 4));
        }
#pragma unroll
        for (int p = 0; p < 4; ++p) {
            int row = wn * 64 + p * 16 + lrow;
            offb[j][p] = (uint32_t)row * 128 + (chsh ^ ((uint32_t)(row & 7) << 4));
        }
    }

    // prologue: fill STAGES-1 stages (8 A-chunks + 8 B-chunks per thread)
#pragma unroll
    for (int s = 0; s < STAGES - 1; ++s) {
#pragma unroll
        for (int i = 0; i < 8; ++i)
            cpa16(sb + s * STAGE_BYTES + dbase_a + i * I_SSTRIDE,
                  aptr + i * I_GSTRIDE);
#pragma unroll
        for (int i = 0; i < 8; ++i)
            cpa16(sb + s * STAGE_BYTES + dbase_b + i * I_SSTRIDE,
                  bptr + i * I_GSTRIDE);
        asm volatile("cp.async.commit_group;" ::: "memory");
        aptr += BK * 2;
        bptr += BK * 2;
    }

    uint32_t cur = sb;
    uint32_t lda = sb + (STAGES - 1) * STAGE_BYTES + dbase_a;
    uint32_t ldb = sb + (STAGES - 1) * STAGE_BYTES + dbase_b;
    const uint32_t wrap = sb + STAGES * STAGE_BYTES;

    // main loop: unconditional loads, interleaved through the k-steps
    for (int kt = 0; kt < NKT - (STAGES - 1); ++kt) {
        asm volatile("cp.async.wait_group %0;" :: "n"(STAGES - 2) : "memory");
        __syncthreads();

        uint32_t sa = cur, sbw = cur + A_TILE_BYTES;

        Frag f0, f1;
        frags_ld(f0, sa, sbw, offa[0], offb[0]);   // j=0: restart tensor pipe

#pragma unroll
        for (int i = 0; i < 4; ++i)                // A chunks 0-3
            cpa16(lda + i * I_SSTRIDE, aptr + i * I_GSTRIDE);

        frags_ld(f1, sa, sbw, offa[1], offb[1]);

#pragma unroll
        for (int i = 4; i < 8; ++i)                // A chunks 4-7
            cpa16(lda + i * I_SSTRIDE, aptr + i * I_GSTRIDE);

        frags_mma(acc, f0);

#pragma unroll
        for (int i = 0; i < 4; ++i)                // B chunks 0-3
            cpa16(ldb + i * I_SSTRIDE, bptr + i * I_GSTRIDE);

        frags_ld(f0, sa, sbw, offa[2], offb[2]);

#pragma unroll
        for (int i = 4; i < 8; ++i)                // B chunks 4-7
            cpa16(ldb + i * I_SSTRIDE, bptr + i * I_GSTRIDE);
        asm volatile("cp.async.commit_group;" ::: "memory");
        aptr += BK * 2;
        bptr += BK * 2;

        frags_mma(acc, f1);
        frags_ld(f1, sa, sbw, offa[3], offb[3]);
        frags_mma(acc, f0);
        frags_mma(acc, f1);

        cur += STAGE_BYTES; if (cur == wrap) cur = sb;
        lda += STAGE_BYTES; if (lda >= wrap) lda -= STAGES * STAGE_BYTES;
        ldb += STAGE_BYTES; if (ldb >= wrap) ldb -= STAGES * STAGE_BYTES;
    }

    // tail: last STAGES-1 ktiles, no loads
#pragma unroll
    for (int t = 0; t < STAGES - 1; ++t) {
        asm volatile("cp.async.wait_group %0;" :: "n"(0) : "memory");
        __syncthreads();
        uint32_t sa = cur, sbw = cur + A_TILE_BYTES;
        Frag f0, f1;
        frags_ld(f0, sa, sbw, offa[0], offb[0]);
        frags_ld(f1, sa, sbw, offa[1], offb[1]);
        frags_mma(acc, f0);
        frags_ld(f0, sa, sbw, offa[2], offb[2]);
        frags_mma(acc, f1);
        frags_ld(f1, sa, sbw, offa[3], offb[3]);
        frags_mma(acc, f0);
        frags_mma(acc, f1);
        cur += STAGE_BYTES; if (cur == wrap) cur = sb;
    }

    // epilogue: scale and store fp32
    float cs = scale[0] * iscale[0];
    int r0 = lid >> 2, c0 = (lid & 3) * 2;
#pragma unroll
    for (int mt = 0; mt < 4; ++mt) {
        size_t row0 = (size_t)tm * BM + wm * 64 + mt * 16 + r0;
#pragma unroll
        for (int nt = 0; nt < 8; ++nt) {
            size_t col = (size_t)tn * BN + wn * 64 + nt * 8 + c0;
            float2 v0, v1;
            v0.x = acc[mt][nt][0] * cs;
            v0.y = acc[mt][nt][1] * cs;
            v1.x = acc[mt][nt][2] * cs;
            v1.y = acc[mt][nt][3] * cs;
            *reinterpret_cast<float2*>(out + row0 * NN + col) = v0;
            *reinterpret_cast<float2*>(out + (row0 + 8) * NN + col) = v1;
        }
    }
}

// ---------------------------------------------------------------------------
extern "C" void kernel_launch(void* const* d_in, const int* in_sizes, int n_in,
                              void* d_out, int out_size) {
    const float* x      = (const float*)d_in[0];
    const int*   w      = (const int*)d_in[1];
    const float* scale  = (const float*)d_in[2];
    const float* iscale = (const float*)d_in[3];
    float* out = (float*)d_out;

    cudaFuncSetAttribute(gemm_kernel, cudaFuncAttributeMaxDynamicSharedMemorySize,
                         SMEM_TOTAL);

    prep_kernel<<<XBLK + WBLK, 256>>>(x, w, iscale);
    gemm_kernel<<<(MM / BM) * (NN / BN), 128, SMEM_TOTAL>>>(out, scale, iscale);
}